// round 9
// baseline (speedup 1.0000x reference)
#include <cuda_runtime.h>
#include <cuda_fp16.h>
#include <cstdint>

#define NEXP   8
#define DIM_S  64
#define HID    256
#define BM     128
#define NTHR   512

// Pre-shuffled fp16 B-fragment streams (built by convw each launch).
// Layout: [c][wn][ks][quarter q4=rg*2+nthalf][lane][j(=nt within half)] u32
//   u32 = {W[k][n], W[k+1][n]},  k = ks*16 + (lane&3)*2 + 8*rg,
//   n = wn*64 + nt*8 + (lane>>2),  nt = (q4&1)*4 + j
__device__ uint32_t g_w1s[NEXP * 4 * 4 * 512];    //  65536 u32 (256 KB)
__device__ uint32_t g_w2s[NEXP * 4 * 16 * 512];   // 262144 u32 (1 MB)

// ---- SMEM (bytes) ----
// A1: fp16 [128 r][64 k], 128 B/row, chunk swizzle: chunk ^= (row&7)
// H1: fp16 [128 r][256 k], 512 B/row, same swizzle (low 3 chunk bits)
#define OFF_A1    0
#define OFF_H1    16384
#define OFF_B1    81920          // f32[256]
#define OFF_B2    82944
#define OFF_W3    83968
#define OFF_PART  84992          // [128 rows][4 wn] f32
#define SMEM_BYTES 87040

__device__ __forceinline__ uint32_t packh2(float lo, float hi) {
    __half2 h = __floats2half2_rn(lo, hi);
    return *reinterpret_cast<uint32_t*>(&h);
}
__device__ __forceinline__ uint32_t smem_u32(const void* p) {
    uint32_t a;
    asm("{ .reg .u64 t; cvta.to.shared.u64 t, %1; cvt.u32.u64 %0, t; }" : "=r"(a) : "l"(p));
    return a;
}
__device__ __forceinline__ void mma_f16(float c[4], const uint32_t* a,
                                        uint32_t b0, uint32_t b1) {
    asm volatile(
        "mma.sync.aligned.m16n8k16.row.col.f32.f16.f16.f32 "
        "{%0,%1,%2,%3}, {%4,%5,%6,%7}, {%8,%9}, {%0,%1,%2,%3};"
        : "+f"(c[0]), "+f"(c[1]), "+f"(c[2]), "+f"(c[3])
        : "r"(a[0]), "r"(a[1]), "r"(a[2]), "r"(a[3]), "r"(b0), "r"(b1));
}
__device__ __forceinline__ void ldmx4(uint32_t* a, uint32_t addr) {
    asm volatile("ldmatrix.sync.aligned.m8n8.x4.shared.b16 {%0,%1,%2,%3}, [%4];"
        : "=r"(a[0]), "=r"(a[1]), "=r"(a[2]), "=r"(a[3]) : "r"(addr));
}

// ---- prologue: build B-fragment streams from fp32 row-major weights ----
__global__ void __launch_bounds__(256)
convw(const float* __restrict__ W1, const float* __restrict__ W2)
{
    int i = blockIdx.x * 256 + threadIdx.x;
    if (i < NEXP * 4 * 4 * 512) {            // W1 stream
        int j = i & 3, lane = (i >> 2) & 31, q4 = (i >> 7) & 3;
        int ks = (i >> 9) & 3, w = (i >> 11) & 3, c = i >> 13;
        int rg = q4 >> 1, nt = (q4 & 1) * 4 + j;
        int n = w * 64 + nt * 8 + (lane >> 2);
        int k = ks * 16 + (lane & 3) * 2 + rg * 8;
        const float* p = W1 + ((size_t)c * DIM_S + k) * HID + n;
        g_w1s[i] = packh2(p[0], p[HID]);
    } else {
        i -= NEXP * 4 * 4 * 512;
        if (i < NEXP * 4 * 16 * 512) {       // W2 stream
            int j = i & 3, lane = (i >> 2) & 31, q4 = (i >> 7) & 3;
            int ks = (i >> 9) & 15, w = (i >> 13) & 3, c = i >> 15;
            int rg = q4 >> 1, nt = (q4 & 1) * 4 + j;
            int n = w * 64 + nt * 8 + (lane >> 2);
            int k = ks * 16 + (lane & 3) * 2 + rg * 8;
            const float* p = W2 + ((size_t)c * HID + k) * HID + n;
            g_w2s[i] = packh2(p[0], p[HID]);
        }
    }
}

// GEMM: acc[2][8][4] += A(rows wm32..wm32+31, K = TOT16*16, smem swizzled
// row-major fp16, ROWB bytes/row) * B(fragment stream, this warp's 64 cols).
template<int TOT16, int ROWB>
__device__ __forceinline__ void gemm(const uint32_t* __restrict__ bs,
                                     uint32_t afb, float acc[2][8][4],
                                     int lane, int wm32)
{
    const int arow = wm32 + ((lane >> 3) & 1) * 8 + (lane & 7);
    const int jj   = lane >> 4;
    const uint32_t abase = afb + arow * ROWB;
    const int      amask = arow & 7;

    uint32_t breg[2][16];   // [ring][nt*2+rg]
    uint32_t areg[2][4];

    auto loadB = [&](int ks, uint32_t* b) {
        const uint4* p = reinterpret_cast<const uint4*>(
            bs + (size_t)ks * 512 + lane * 4);
        uint4 v0 = __ldg(p);        // rg0, nt0-3
        uint4 v1 = __ldg(p + 32);   // rg0, nt4-7
        uint4 v2 = __ldg(p + 64);   // rg1, nt0-3
        uint4 v3 = __ldg(p + 96);   // rg1, nt4-7
        b[0]  = v0.x; b[2]  = v0.y; b[4]  = v0.z; b[6]  = v0.w;
        b[8]  = v1.x; b[10] = v1.y; b[12] = v1.z; b[14] = v1.w;
        b[1]  = v2.x; b[3]  = v2.y; b[5]  = v2.z; b[7]  = v2.w;
        b[9]  = v3.x; b[11] = v3.y; b[13] = v3.z; b[15] = v3.w;
    };
    auto loadA = [&](int ks, int mt, uint32_t* a) {
        int chunk = (2 * ks + jj) ^ amask;
        ldmx4(a, abase + mt * 16 * ROWB + chunk * 16);
    };

    loadB(0, breg[0]);
    loadA(0, 0, areg[0]);

    #pragma unroll
    for (int ks = 0; ks < TOT16; ks++) {
        if (ks + 1 < TOT16) loadB(ks + 1, breg[(ks + 1) & 1]);
        const uint32_t* b = breg[ks & 1];
        #pragma unroll
        for (int mt = 0; mt < 2; mt++) {
            if (!(mt == 1 && ks + 1 == TOT16))
                loadA(mt == 1 ? ks + 1 : ks, (mt + 1) & 1, areg[(mt + 1) & 1]);
            const uint32_t* a = areg[mt & 1];
            #pragma unroll
            for (int nt = 0; nt < 8; nt++)
                mma_f16(acc[mt][nt], a, b[nt * 2], b[nt * 2 + 1]);
        }
    }
}

__global__ void __launch_bounds__(NTHR, 1)
moe_disc_mma(const float* __restrict__ st,
             const float* __restrict__ b1, const float* __restrict__ b2,
             const float* __restrict__ W3, const float* __restrict__ b3,
             float* __restrict__ out)
{
    extern __shared__ char smem[];
    float* smf = reinterpret_cast<float*>(smem);
    const uint32_t sb = smem_u32(smem);
    const int tid  = threadIdx.x;
    const int wid  = tid >> 5;
    const int lane = tid & 31;
    const int wm   = wid >> 2;        // 0..3 : 32-row slice
    const int wn   = wid & 3;         // 0..3 : 64-col block
    const int wm32 = wm * 32;
    const int c    = blockIdx.y;
    const int m0   = blockIdx.x * BM;

    // ---- stage biases / w3 / A1 ----
    if (tid < 256) {
        smf[(OFF_B1 >> 2) + tid] = b1[c * HID + tid];
        smf[(OFF_B2 >> 2) + tid] = b2[c * HID + tid];
        smf[(OFF_W3 >> 2) + tid] = W3[c * HID + tid];
    }
    #pragma unroll
    for (int i = 0; i < 4; i++) {
        int idx = tid + i * NTHR;       // 0..2047 float4
        int row = idx >> 4, f4 = idx & 15;
        float4 v = *reinterpret_cast<const float4*>(
            st + (size_t)(m0 + row) * DIM_S + f4 * 4);
        uint32_t byte = OFF_A1 + row * 128
                      + (uint32_t)(((f4 >> 1) ^ (row & 7)) * 16 + 8 * (f4 & 1));
        *reinterpret_cast<uint2*>(smem + byte) =
            make_uint2(packh2(v.x, v.y), packh2(v.z, v.w));
    }
    __syncthreads();

    float acc[2][8][4];
    #pragma unroll
    for (int a = 0; a < 2; a++)
        #pragma unroll
        for (int b = 0; b < 8; b++)
            #pragma unroll
            for (int e = 0; e < 4; e++) acc[a][b][e] = 0.f;

    // ---- layer 1 GEMM (K = 64) ----
    gemm<4, 128>(g_w1s + ((size_t)(c * 4 + wn)) * 2048, sb + OFF_A1,
                 acc, lane, wm32);

    // ---- epilogue 1: H1 = fp16(relu(acc + b1)), swizzled row-major ----
    {
        float b1v[16];
        #pragma unroll
        for (int nt = 0; nt < 8; nt++) {
            int k0 = wn * 64 + nt * 8 + 2 * (lane & 3);
            b1v[nt * 2]     = smf[(OFF_B1 >> 2) + k0];
            b1v[nt * 2 + 1] = smf[(OFF_B1 >> 2) + k0 + 1];
        }
        #pragma unroll
        for (int mt = 0; mt < 2; mt++)
            #pragma unroll
            for (int nt = 0; nt < 8; nt++) {
                int r0 = wm32 + mt * 16 + (lane >> 2);
                int chunk = wn * 8 + nt;
                uint32_t p0 = packh2(
                    fmaxf(acc[mt][nt][0] + b1v[nt * 2], 0.f),
                    fmaxf(acc[mt][nt][1] + b1v[nt * 2 + 1], 0.f));
                uint32_t p1 = packh2(
                    fmaxf(acc[mt][nt][2] + b1v[nt * 2], 0.f),
                    fmaxf(acc[mt][nt][3] + b1v[nt * 2 + 1], 0.f));
                uint32_t by0 = OFF_H1 + r0 * 512
                             + ((chunk ^ (r0 & 7)) * 16) + 4 * (lane & 3);
                int r1 = r0 + 8;
                uint32_t by1 = OFF_H1 + r1 * 512
                             + ((chunk ^ (r1 & 7)) * 16) + 4 * (lane & 3);
                *reinterpret_cast<uint32_t*>(smem + by0) = p0;
                *reinterpret_cast<uint32_t*>(smem + by1) = p1;
            }
    }
    #pragma unroll
    for (int a = 0; a < 2; a++)
        #pragma unroll
        for (int b = 0; b < 8; b++)
            #pragma unroll
            for (int e = 0; e < 4; e++) acc[a][b][e] = 0.f;

    __syncthreads();   // H1 visible

    // ---- layer 2 GEMM (K = 256) ----
    gemm<16, 512>(g_w2s + ((size_t)(c * 4 + wn)) * 8192, sb + OFF_H1,
                  acc, lane, wm32);

    // ---- epilogue 2: d = relu(acc + b2) . w3, reduce, + b3 ----
    {
        float b2v[16], w3v[16];
        #pragma unroll
        for (int nt = 0; nt < 8; nt++) {
            int k0 = wn * 64 + nt * 8 + 2 * (lane & 3);
            b2v[nt * 2]     = smf[(OFF_B2 >> 2) + k0];
            b2v[nt * 2 + 1] = smf[(OFF_B2 >> 2) + k0 + 1];
            w3v[nt * 2]     = smf[(OFF_W3 >> 2) + k0];
            w3v[nt * 2 + 1] = smf[(OFF_W3 >> 2) + k0 + 1];
        }
        float p[2][2];
        #pragma unroll
        for (int mt = 0; mt < 2; mt++) { p[mt][0] = 0.f; p[mt][1] = 0.f; }
        #pragma unroll
        for (int mt = 0; mt < 2; mt++)
            #pragma unroll
            for (int nt = 0; nt < 8; nt++) {
                p[mt][0] += fmaxf(acc[mt][nt][0] + b2v[nt * 2], 0.f)     * w3v[nt * 2]
                          + fmaxf(acc[mt][nt][1] + b2v[nt * 2 + 1], 0.f) * w3v[nt * 2 + 1];
                p[mt][1] += fmaxf(acc[mt][nt][2] + b2v[nt * 2], 0.f)     * w3v[nt * 2]
                          + fmaxf(acc[mt][nt][3] + b2v[nt * 2 + 1], 0.f) * w3v[nt * 2 + 1];
            }
        #pragma unroll
        for (int off = 1; off <= 2; off <<= 1)
            #pragma unroll
            for (int mt = 0; mt < 2; mt++) {
                p[mt][0] += __shfl_xor_sync(0xFFFFFFFFu, p[mt][0], off);
                p[mt][1] += __shfl_xor_sync(0xFFFFFFFFu, p[mt][1], off);
            }
        if ((lane & 3) == 0) {
            #pragma unroll
            for (int mt = 0; mt < 2; mt++)
                #pragma unroll
                for (int h = 0; h < 2; h++) {
                    int row = wm32 + mt * 16 + (lane >> 2) + 8 * h;
                    smf[(OFF_PART >> 2) + row * 4 + wn] = p[mt][h];
                }
        }
    }
    __syncthreads();
    if (tid < BM) {
        const float* q = smf + (OFF_PART >> 2) + tid * 4;
        out[(size_t)(m0 + tid) * NEXP + c] = q[0] + q[1] + q[2] + q[3] + b3[c];
    }
}

extern "C" void kernel_launch(void* const* d_in, const int* in_sizes, int n_in,
                              void* d_out, int out_size)
{
    const float* st = (const float*)d_in[0];
    const float* W1 = (const float*)d_in[1];
    const float* b1 = (const float*)d_in[2];
    const float* W2 = (const float*)d_in[3];
    const float* b2 = (const float*)d_in[4];
    const float* W3 = (const float*)d_in[5];
    const float* b3 = (const float*)d_in[6];
    float* out = (float*)d_out;

    const int total = NEXP * 4 * 4 * 512 + NEXP * 4 * 16 * 512;  // 327680
    convw<<<(total + 255) / 256, 256>>>(W1, W2);

    cudaFuncSetAttribute(moe_disc_mma,
                         cudaFuncAttributeMaxDynamicSharedMemorySize, SMEM_BYTES);
    dim3 grid(65536 / BM, NEXP);
    moe_disc_mma<<<grid, NTHR, SMEM_BYTES>>>(st, b1, b2, W3, b3, out);
}

// round 10
// speedup vs baseline: 1.0396x; 1.0396x over previous
#include <cuda_runtime.h>
#include <cuda_fp16.h>
#include <cstdint>

#define NEXP   8
#define DIM_S  64
#define HID    256
#define BM     128
#define NTHR   256

// Pre-shuffled fp16 B-fragment streams (built by convw each launch).
// Layout: [c][wn][ks][quarter q4=rg*2+nthalf][lane][j(=nt within half)] u32
//   u32 = {W[k][n], W[k+1][n]},  k = ks*16 + (lane&3)*2 + 8*rg,
//   n = wn*64 + nt*8 + (lane>>2),  nt = (q4&1)*4 + j
__device__ uint32_t g_w1s[NEXP * 4 * 4 * 512];    //  65536 u32 (256 KB)
__device__ uint32_t g_w2s[NEXP * 4 * 16 * 512];   // 262144 u32 (1 MB)

// ---- SMEM (bytes) ----
// A1: fp16 [128 r][64 k], 128 B/row, chunk swizzle: chunk ^= (row&7)
// H1: fp16 [128 r][256 k], 512 B/row, same swizzle (low 3 chunk bits)
#define OFF_A1    0
#define OFF_H1    16384
#define OFF_B1    81920          // f32[256]
#define OFF_B2    82944
#define OFF_W3    83968
#define OFF_PART  84992          // [128 rows][4 wn] f32
#define SMEM_BYTES 87040

__device__ __forceinline__ uint32_t packh2(float lo, float hi) {
    __half2 h = __floats2half2_rn(lo, hi);
    return *reinterpret_cast<uint32_t*>(&h);
}
__device__ __forceinline__ uint32_t smem_u32(const void* p) {
    uint32_t a;
    asm("{ .reg .u64 t; cvta.to.shared.u64 t, %1; cvt.u32.u64 %0, t; }" : "=r"(a) : "l"(p));
    return a;
}
__device__ __forceinline__ void mma_f16(float c[4], const uint32_t* a,
                                        uint32_t b0, uint32_t b1) {
    asm volatile(
        "mma.sync.aligned.m16n8k16.row.col.f32.f16.f16.f32 "
        "{%0,%1,%2,%3}, {%4,%5,%6,%7}, {%8,%9}, {%0,%1,%2,%3};"
        : "+f"(c[0]), "+f"(c[1]), "+f"(c[2]), "+f"(c[3])
        : "r"(a[0]), "r"(a[1]), "r"(a[2]), "r"(a[3]), "r"(b0), "r"(b1));
}
__device__ __forceinline__ void ldmx4(uint32_t* a, uint32_t addr) {
    asm volatile("ldmatrix.sync.aligned.m8n8.x4.shared.b16 {%0,%1,%2,%3}, [%4];"
        : "=r"(a[0]), "=r"(a[1]), "=r"(a[2]), "=r"(a[3]) : "r"(addr));
}

// Load one ks-step of B fragments (4 coalesced LDG.128).
__device__ __forceinline__ void loadBfrag(const uint32_t* __restrict__ bs,
                                          int ks, int lane, uint32_t* b) {
    const uint4* p = reinterpret_cast<const uint4*>(
        bs + (size_t)ks * 512 + lane * 4);
    uint4 v0 = __ldg(p);        // rg0, nt0-3
    uint4 v1 = __ldg(p + 32);   // rg0, nt4-7
    uint4 v2 = __ldg(p + 64);   // rg1, nt0-3
    uint4 v3 = __ldg(p + 96);   // rg1, nt4-7
    b[0]  = v0.x; b[2]  = v0.y; b[4]  = v0.z; b[6]  = v0.w;
    b[8]  = v1.x; b[10] = v1.y; b[12] = v1.z; b[14] = v1.w;
    b[1]  = v2.x; b[3]  = v2.y; b[5]  = v2.z; b[7]  = v2.w;
    b[9]  = v3.x; b[11] = v3.y; b[13] = v3.z; b[15] = v3.w;
}

// ---- prologue: build B-fragment streams from fp32 row-major weights ----
__global__ void __launch_bounds__(NTHR)
convw(const float* __restrict__ W1, const float* __restrict__ W2)
{
    int i = blockIdx.x * NTHR + threadIdx.x;
    if (i < NEXP * 4 * 4 * 512) {            // W1 stream
        int j = i & 3, lane = (i >> 2) & 31, q4 = (i >> 7) & 3;
        int ks = (i >> 9) & 3, w = (i >> 11) & 3, c = i >> 13;
        int rg = q4 >> 1, nt = (q4 & 1) * 4 + j;
        int n = w * 64 + nt * 8 + (lane >> 2);
        int k = ks * 16 + (lane & 3) * 2 + rg * 8;
        const float* p = W1 + ((size_t)c * DIM_S + k) * HID + n;
        g_w1s[i] = packh2(p[0], p[HID]);
    } else {
        i -= NEXP * 4 * 4 * 512;
        if (i < NEXP * 4 * 16 * 512) {       // W2 stream
            int j = i & 3, lane = (i >> 2) & 31, q4 = (i >> 7) & 3;
            int ks = (i >> 9) & 15, w = (i >> 13) & 3, c = i >> 15;
            int rg = q4 >> 1, nt = (q4 & 1) * 4 + j;
            int n = w * 64 + nt * 8 + (lane >> 2);
            int k = ks * 16 + (lane & 3) * 2 + rg * 8;
            const float* p = W2 + ((size_t)c * HID + k) * HID + n;
            g_w2s[i] = packh2(p[0], p[HID]);
        }
    }
}

// GEMM: acc[4][8][4] += A(rows wm64..+63, K = TOT16*16, smem swizzled
// row-major fp16, ROWB bytes/row) * B(fragment stream, this warp's 64 cols).
// breg[0], breg[1] must be preloaded by the caller (ks = 0, 1).
template<int TOT16, int ROWB>
__device__ __forceinline__ void gemm(const uint32_t* __restrict__ bs,
                                     uint32_t afb, float acc[4][8][4],
                                     int lane, int wm64, uint32_t breg[3][16])
{
    const int arow = wm64 + ((lane >> 3) & 1) * 8 + (lane & 7);
    const int jj   = lane >> 4;
    const uint32_t abase = afb + arow * ROWB;
    const int      amask = arow & 7;

    uint32_t areg[2][4];

    auto loadA = [&](int ks, int mt, uint32_t* a) {
        int chunk = (2 * ks + jj) ^ amask;
        ldmx4(a, abase + mt * 16 * ROWB + chunk * 16);
    };

    loadA(0, 0, areg[0]);

    #pragma unroll
    for (int ks = 0; ks < TOT16; ks++) {
        if (ks + 2 < TOT16) loadBfrag(bs, ks + 2, lane, breg[(ks + 2) % 3]);
        const uint32_t* b = breg[ks % 3];
        #pragma unroll
        for (int mt = 0; mt < 4; mt++) {
            if (!(mt == 3 && ks + 1 == TOT16))
                loadA(mt == 3 ? ks + 1 : ks, (mt + 1) & 3, areg[(mt + 1) & 1]);
            const uint32_t* a = areg[mt & 1];
            #pragma unroll
            for (int nt = 0; nt < 8; nt++)
                mma_f16(acc[mt][nt], a, b[nt * 2], b[nt * 2 + 1]);
        }
    }
}

__global__ void __launch_bounds__(NTHR, 1)
moe_disc_mma(const float* __restrict__ st,
             const float* __restrict__ b1, const float* __restrict__ b2,
             const float* __restrict__ W3, const float* __restrict__ b3,
             float* __restrict__ out)
{
    extern __shared__ char smem[];
    float* smf = reinterpret_cast<float*>(smem);
    const uint32_t sb = smem_u32(smem);
    const int tid  = threadIdx.x;
    const int wid  = tid >> 5;
    const int lane = tid & 31;
    const int wm   = wid >> 2;        // 0..1 : row half
    const int wn   = wid & 3;         // 0..3 : 64-col block
    const int wm64 = wm * 64;
    const int c    = blockIdx.y;
    const int m0   = blockIdx.x * BM;

    const uint32_t* bs1 = g_w1s + ((size_t)(c * 4 + wn)) * 2048;
    const uint32_t* bs2 = g_w2s + ((size_t)(c * 4 + wn)) * 8192;

    // ---- issue GEMM1's first two B k-steps immediately (fly under staging) ----
    uint32_t breg[3][16];
    loadBfrag(bs1, 0, lane, breg[0]);
    loadBfrag(bs1, 1, lane, breg[1]);

    // ---- stage biases / w3 / A1 ----
    smf[(OFF_B1 >> 2) + tid] = b1[c * HID + tid];
    smf[(OFF_B2 >> 2) + tid] = b2[c * HID + tid];
    smf[(OFF_W3 >> 2) + tid] = W3[c * HID + tid];

    #pragma unroll
    for (int i = 0; i < 8; i++) {
        int idx = tid + i * NTHR;       // 0..2047 float4
        int row = idx >> 4, f4 = idx & 15;
        float4 v = *reinterpret_cast<const float4*>(
            st + (size_t)(m0 + row) * DIM_S + f4 * 4);
        uint32_t byte = OFF_A1 + row * 128
                      + (uint32_t)(((f4 >> 1) ^ (row & 7)) * 16 + 8 * (f4 & 1));
        *reinterpret_cast<uint2*>(smem + byte) =
            make_uint2(packh2(v.x, v.y), packh2(v.z, v.w));
    }
    __syncthreads();

    float acc[4][8][4];
    #pragma unroll
    for (int a = 0; a < 4; a++)
        #pragma unroll
        for (int b = 0; b < 8; b++)
            #pragma unroll
            for (int e = 0; e < 4; e++) acc[a][b][e] = 0.f;

    // ---- layer 1 GEMM (K = 64) ----
    gemm<4, 128>(bs1, sb + OFF_A1, acc, lane, wm64, breg);

    // ---- preload GEMM2's first two B k-steps (fly under epilogue 1) ----
    loadBfrag(bs2, 0, lane, breg[0]);
    loadBfrag(bs2, 1, lane, breg[1]);

    // ---- epilogue 1: H1 = fp16(relu(acc + b1)), swizzled row-major ----
    {
        float b1v[16];
        #pragma unroll
        for (int nt = 0; nt < 8; nt++) {
            int k0 = wn * 64 + nt * 8 + 2 * (lane & 3);
            b1v[nt * 2]     = smf[(OFF_B1 >> 2) + k0];
            b1v[nt * 2 + 1] = smf[(OFF_B1 >> 2) + k0 + 1];
        }
        #pragma unroll
        for (int mt = 0; mt < 4; mt++)
            #pragma unroll
            for (int nt = 0; nt < 8; nt++) {
                int r0 = wm64 + mt * 16 + (lane >> 2);
                int chunk = wn * 8 + nt;
                uint32_t p0 = packh2(
                    fmaxf(acc[mt][nt][0] + b1v[nt * 2], 0.f),
                    fmaxf(acc[mt][nt][1] + b1v[nt * 2 + 1], 0.f));
                uint32_t p1 = packh2(
                    fmaxf(acc[mt][nt][2] + b1v[nt * 2], 0.f),
                    fmaxf(acc[mt][nt][3] + b1v[nt * 2 + 1], 0.f));
                uint32_t by0 = OFF_H1 + r0 * 512
                             + ((chunk ^ (r0 & 7)) * 16) + 4 * (lane & 3);
                int r1 = r0 + 8;
                uint32_t by1 = OFF_H1 + r1 * 512
                             + ((chunk ^ (r1 & 7)) * 16) + 4 * (lane & 3);
                *reinterpret_cast<uint32_t*>(smem + by0) = p0;
                *reinterpret_cast<uint32_t*>(smem + by1) = p1;
            }
    }
    #pragma unroll
    for (int a = 0; a < 4; a++)
        #pragma unroll
        for (int b = 0; b < 8; b++)
            #pragma unroll
            for (int e = 0; e < 4; e++) acc[a][b][e] = 0.f;

    __syncthreads();   // H1 visible to all warps

    // ---- layer 2 GEMM (K = 256) ----
    gemm<16, 512>(bs2, sb + OFF_H1, acc, lane, wm64, breg);

    // ---- epilogue 2: d = relu(acc + b2) . w3, reduce, + b3 ----
    {
        float b2v[16], w3v[16];
        #pragma unroll
        for (int nt = 0; nt < 8; nt++) {
            int k0 = wn * 64 + nt * 8 + 2 * (lane & 3);
            b2v[nt * 2]     = smf[(OFF_B2 >> 2) + k0];
            b2v[nt * 2 + 1] = smf[(OFF_B2 >> 2) + k0 + 1];
            w3v[nt * 2]     = smf[(OFF_W3 >> 2) + k0];
            w3v[nt * 2 + 1] = smf[(OFF_W3 >> 2) + k0 + 1];
        }
        float p[4][2];
        #pragma unroll
        for (int mt = 0; mt < 4; mt++) { p[mt][0] = 0.f; p[mt][1] = 0.f; }
        #pragma unroll
        for (int mt = 0; mt < 4; mt++)
            #pragma unroll
            for (int nt = 0; nt < 8; nt++) {
                p[mt][0] += fmaxf(acc[mt][nt][0] + b2v[nt * 2], 0.f)     * w3v[nt * 2]
                          + fmaxf(acc[mt][nt][1] + b2v[nt * 2 + 1], 0.f) * w3v[nt * 2 + 1];
                p[mt][1] += fmaxf(acc[mt][nt][2] + b2v[nt * 2], 0.f)     * w3v[nt * 2]
                          + fmaxf(acc[mt][nt][3] + b2v[nt * 2 + 1], 0.f) * w3v[nt * 2 + 1];
            }
        #pragma unroll
        for (int off = 1; off <= 2; off <<= 1)
            #pragma unroll
            for (int mt = 0; mt < 4; mt++) {
                p[mt][0] += __shfl_xor_sync(0xFFFFFFFFu, p[mt][0], off);
                p[mt][1] += __shfl_xor_sync(0xFFFFFFFFu, p[mt][1], off);
            }
        if ((lane & 3) == 0) {
            #pragma unroll
            for (int mt = 0; mt < 4; mt++)
                #pragma unroll
                for (int h = 0; h < 2; h++) {
                    int row = wm64 + mt * 16 + (lane >> 2) + 8 * h;
                    smf[(OFF_PART >> 2) + row * 4 + wn] = p[mt][h];
                }
        }
    }
    __syncthreads();
    if (tid < BM) {
        const float* q = smf + (OFF_PART >> 2) + tid * 4;
        out[(size_t)(m0 + tid) * NEXP + c] = q[0] + q[1] + q[2] + q[3] + b3[c];
    }
}

extern "C" void kernel_launch(void* const* d_in, const int* in_sizes, int n_in,
                              void* d_out, int out_size)
{
    const float* st = (const float*)d_in[0];
    const float* W1 = (const float*)d_in[1];
    const float* b1 = (const float*)d_in[2];
    const float* W2 = (const float*)d_in[3];
    const float* b2 = (const float*)d_in[4];
    const float* W3 = (const float*)d_in[5];
    const float* b3 = (const float*)d_in[6];
    float* out = (float*)d_out;

    const int total = NEXP * 4 * 4 * 512 + NEXP * 4 * 16 * 512;  // 327680
    convw<<<(total + NTHR - 1) / NTHR, NTHR>>>(W1, W2);

    cudaFuncSetAttribute(moe_disc_mma,
                         cudaFuncAttributeMaxDynamicSharedMemorySize, SMEM_BYTES);
    dim3 grid(65536 / BM, NEXP);
    moe_disc_mma<<<grid, NTHR, SMEM_BYTES>>>(st, b1, b2, W3, b3, out);
}

// round 11
// speedup vs baseline: 1.1125x; 1.0701x over previous
#include <cuda_runtime.h>
#include <cuda_fp16.h>
#include <cstdint>

#define NEXP   8
#define DIM_S  64
#define HID    256
#define BM     64
#define NTHR   256

// Pre-shuffled fp16 B-fragment streams, 32-col warp granularity.
// u32 at [c][w][ks][rg][lane][j]:  value = {W[k][n], W[k+1][n]}
//   k = ks*16 + (lane&3)*2 + rg*8,  n = w*32 + j*8 + (lane>>2)
__device__ uint32_t g_w1s[NEXP * 8 * 4 * 2 * 128];    //  65536 u32
__device__ uint32_t g_w2s[NEXP * 8 * 16 * 2 * 128];   // 262144 u32

// ---- SMEM (bytes) ----
// A1: fp16 [64 r][64 k], 128 B/row, chunk(16B) swizzle: chunk ^= (row&7)
// H1: fp16 [64 r][256 k], 512 B/row, same swizzle (low 3 chunk bits)
#define OFF_A1    0
#define OFF_H1    8192
#define OFF_B1    40960          // f32[256]
#define OFF_B2    41984
#define OFF_W3    43008
#define OFF_PART  44032          // [64 rows][8 w] f32
#define SMEM_BYTES 46080

__device__ __forceinline__ uint32_t packh2(float lo, float hi) {
    __half2 h = __floats2half2_rn(lo, hi);
    return *reinterpret_cast<uint32_t*>(&h);
}
__device__ __forceinline__ uint32_t smem_u32(const void* p) {
    uint32_t a;
    asm("{ .reg .u64 t; cvta.to.shared.u64 t, %1; cvt.u32.u64 %0, t; }" : "=r"(a) : "l"(p));
    return a;
}
__device__ __forceinline__ void mma_f16(float c[4], const uint32_t* a,
                                        uint32_t b0, uint32_t b1) {
    asm volatile(
        "mma.sync.aligned.m16n8k16.row.col.f32.f16.f16.f32 "
        "{%0,%1,%2,%3}, {%4,%5,%6,%7}, {%8,%9}, {%0,%1,%2,%3};"
        : "+f"(c[0]), "+f"(c[1]), "+f"(c[2]), "+f"(c[3])
        : "r"(a[0]), "r"(a[1]), "r"(a[2]), "r"(a[3]), "r"(b0), "r"(b1));
}
__device__ __forceinline__ void ldmx4(uint32_t* a, uint32_t addr) {
    asm volatile("ldmatrix.sync.aligned.m8n8.x4.shared.b16 {%0,%1,%2,%3}, [%4];"
        : "=r"(a[0]), "=r"(a[1]), "=r"(a[2]), "=r"(a[3]) : "r"(addr));
}

// Load one ks-step of B fragments (2 coalesced LDG.128).  b[nt*2+rg]
__device__ __forceinline__ void loadBfrag(const uint32_t* __restrict__ bs,
                                          int ks, int lane, uint32_t* b) {
    const uint4* p = reinterpret_cast<const uint4*>(
        bs + (size_t)ks * 256 + lane * 4);
    uint4 v0 = __ldg(p);        // rg0, nt0-3
    uint4 v1 = __ldg(p + 32);   // rg1, nt0-3
    b[0] = v0.x; b[2] = v0.y; b[4] = v0.z; b[6] = v0.w;
    b[1] = v1.x; b[3] = v1.y; b[5] = v1.z; b[7] = v1.w;
}

// ---- prologue: build B-fragment streams from fp32 row-major weights ----
__global__ void __launch_bounds__(NTHR)
convw(const float* __restrict__ W1, const float* __restrict__ W2)
{
    int i = blockIdx.x * NTHR + threadIdx.x;
    if (i < NEXP * 8 * 4 * 2 * 128) {        // W1 stream
        int j = i & 3, lane = (i >> 2) & 31, rg = (i >> 7) & 1;
        int ks = (i >> 8) & 3, w = (i >> 10) & 7, c = i >> 13;
        int k = ks * 16 + (lane & 3) * 2 + rg * 8;
        int n = w * 32 + j * 8 + (lane >> 2);
        const float* p = W1 + ((size_t)c * DIM_S + k) * HID + n;
        g_w1s[i] = packh2(p[0], p[HID]);
    } else {
        i -= NEXP * 8 * 4 * 2 * 128;
        if (i < NEXP * 8 * 16 * 2 * 128) {   // W2 stream
            int j = i & 3, lane = (i >> 2) & 31, rg = (i >> 7) & 1;
            int ks = (i >> 8) & 15, w = (i >> 12) & 7, c = i >> 15;
            int k = ks * 16 + (lane & 3) * 2 + rg * 8;
            int n = w * 32 + j * 8 + (lane >> 2);
            const float* p = W2 + ((size_t)c * HID + k) * HID + n;
            g_w2s[i] = packh2(p[0], p[HID]);
        }
    }
}

// GEMM: acc[4][4][4] += A(rows 0..63, K = TOT16*16, smem swizzled row-major
// fp16, ROWB bytes/row) * B(fragment stream, this warp's 32 cols).
// breg[0], breg[1] preloaded by caller (ks = 0, 1).
template<int TOT16, int ROWB>
__device__ __forceinline__ void gemm(const uint32_t* __restrict__ bs,
                                     uint32_t afb, float acc[4][4][4],
                                     int lane, uint32_t breg[3][8])
{
    const int arow = ((lane >> 3) & 1) * 8 + (lane & 7);
    const int jj   = lane >> 4;
    const uint32_t abase = afb + arow * ROWB;
    const int      amask = arow & 7;

    uint32_t areg[2][4];

    auto loadA = [&](int ks, int mt, uint32_t* a) {
        int chunk = (2 * ks + jj) ^ amask;
        ldmx4(a, abase + mt * 16 * ROWB + chunk * 16);
    };

    loadA(0, 0, areg[0]);

    #pragma unroll
    for (int ks = 0; ks < TOT16; ks++) {
        if (ks + 2 < TOT16) loadBfrag(bs, ks + 2, lane, breg[(ks + 2) % 3]);
        const uint32_t* b = breg[ks % 3];
        #pragma unroll
        for (int mt = 0; mt < 4; mt++) {
            if (!(mt == 3 && ks + 1 == TOT16))
                loadA(mt == 3 ? ks + 1 : ks, (mt + 1) & 3, areg[(mt + 1) & 1]);
            const uint32_t* a = areg[mt & 1];
            #pragma unroll
            for (int nt = 0; nt < 4; nt++)
                mma_f16(acc[mt][nt], a, b[nt * 2], b[nt * 2 + 1]);
        }
    }
}

__global__ void __launch_bounds__(NTHR, 2)
moe_disc_mma(const float* __restrict__ st,
             const float* __restrict__ b1, const float* __restrict__ b2,
             const float* __restrict__ W3, const float* __restrict__ b3,
             float* __restrict__ out)
{
    extern __shared__ char smem[];
    float* smf = reinterpret_cast<float*>(smem);
    const uint32_t sb = smem_u32(smem);
    const int tid  = threadIdx.x;
    const int w    = tid >> 5;        // 0..7 : 32-col block
    const int lane = tid & 31;
    const int c    = blockIdx.y;
    const int m0   = blockIdx.x * BM;

    const uint32_t* bs1 = g_w1s + ((size_t)(c * 8 + w)) * 1024;
    const uint32_t* bs2 = g_w2s + ((size_t)(c * 8 + w)) * 4096;

    // GEMM1's first two B k-steps fly under staging
    uint32_t breg[3][8];
    loadBfrag(bs1, 0, lane, breg[0]);
    loadBfrag(bs1, 1, lane, breg[1]);

    // ---- stage biases / w3 / A1 ----
    smf[(OFF_B1 >> 2) + tid] = b1[c * HID + tid];
    smf[(OFF_B2 >> 2) + tid] = b2[c * HID + tid];
    smf[(OFF_W3 >> 2) + tid] = W3[c * HID + tid];

    #pragma unroll
    for (int i = 0; i < 4; i++) {
        int idx = tid + i * NTHR;       // 0..1023 float4
        int row = idx >> 4, f4 = idx & 15;
        float4 v = *reinterpret_cast<const float4*>(
            st + (size_t)(m0 + row) * DIM_S + f4 * 4);
        uint32_t byte = OFF_A1 + row * 128
                      + (uint32_t)(((f4 >> 1) ^ (row & 7)) * 16 + 8 * (f4 & 1));
        *reinterpret_cast<uint2*>(smem + byte) =
            make_uint2(packh2(v.x, v.y), packh2(v.z, v.w));
    }
    __syncthreads();

    float acc[4][4][4];
    #pragma unroll
    for (int a = 0; a < 4; a++)
        #pragma unroll
        for (int b = 0; b < 4; b++)
            #pragma unroll
            for (int e = 0; e < 4; e++) acc[a][b][e] = 0.f;

    // ---- layer 1 GEMM (K = 64) ----
    gemm<4, 128>(bs1, sb + OFF_A1, acc, lane, breg);

    // GEMM2's first two B k-steps fly under epilogue 1
    loadBfrag(bs2, 0, lane, breg[0]);
    loadBfrag(bs2, 1, lane, breg[1]);

    // ---- epilogue 1: H1 = fp16(relu(acc + b1)), swizzled row-major ----
    // phys col of acc[mt][nt][reg] = w*32 + nt*8 + 2*(lane&3) + (reg&1)
    {
        float b1v[8];
        #pragma unroll
        for (int nt = 0; nt < 4; nt++) {
            int k0 = w * 32 + nt * 8 + 2 * (lane & 3);
            b1v[nt * 2]     = smf[(OFF_B1 >> 2) + k0];
            b1v[nt * 2 + 1] = smf[(OFF_B1 >> 2) + k0 + 1];
        }
        #pragma unroll
        for (int mt = 0; mt < 4; mt++)
            #pragma unroll
            for (int nt = 0; nt < 4; nt++) {
                int r0 = mt * 16 + (lane >> 2);
                int chunk = w * 4 + nt;
                uint32_t p0 = packh2(
                    fmaxf(acc[mt][nt][0] + b1v[nt * 2], 0.f),
                    fmaxf(acc[mt][nt][1] + b1v[nt * 2 + 1], 0.f));
                uint32_t p1 = packh2(
                    fmaxf(acc[mt][nt][2] + b1v[nt * 2], 0.f),
                    fmaxf(acc[mt][nt][3] + b1v[nt * 2 + 1], 0.f));
                uint32_t by0 = OFF_H1 + r0 * 512
                             + ((chunk ^ (r0 & 7)) * 16) + 4 * (lane & 3);
                int r1 = r0 + 8;
                uint32_t by1 = OFF_H1 + r1 * 512
                             + ((chunk ^ (r1 & 7)) * 16) + 4 * (lane & 3);
                *reinterpret_cast<uint32_t*>(smem + by0) = p0;
                *reinterpret_cast<uint32_t*>(smem + by1) = p1;
            }
    }
    #pragma unroll
    for (int a = 0; a < 4; a++)
        #pragma unroll
        for (int b = 0; b < 4; b++)
            #pragma unroll
            for (int e = 0; e < 4; e++) acc[a][b][e] = 0.f;

    __syncthreads();   // H1 visible

    // ---- layer 2 GEMM (K = 256) ----
    gemm<16, 512>(bs2, sb + OFF_H1, acc, lane, breg);

    // ---- epilogue 2: d = relu(acc + b2) . w3, reduce, + b3 ----
    {
        float b2v[8], w3v[8];
        #pragma unroll
        for (int nt = 0; nt < 4; nt++) {
            int k0 = w * 32 + nt * 8 + 2 * (lane & 3);
            b2v[nt * 2]     = smf[(OFF_B2 >> 2) + k0];
            b2v[nt * 2 + 1] = smf[(OFF_B2 >> 2) + k0 + 1];
            w3v[nt * 2]     = smf[(OFF_W3 >> 2) + k0];
            w3v[nt * 2 + 1] = smf[(OFF_W3 >> 2) + k0 + 1];
        }
        float p[4][2];
        #pragma unroll
        for (int mt = 0; mt < 4; mt++) { p[mt][0] = 0.f; p[mt][1] = 0.f; }
        #pragma unroll
        for (int mt = 0; mt < 4; mt++)
            #pragma unroll
            for (int nt = 0; nt < 4; nt++) {
                p[mt][0] += fmaxf(acc[mt][nt][0] + b2v[nt * 2], 0.f)     * w3v[nt * 2]
                          + fmaxf(acc[mt][nt][1] + b2v[nt * 2 + 1], 0.f) * w3v[nt * 2 + 1];
                p[mt][1] += fmaxf(acc[mt][nt][2] + b2v[nt * 2], 0.f)     * w3v[nt * 2]
                          + fmaxf(acc[mt][nt][3] + b2v[nt * 2 + 1], 0.f) * w3v[nt * 2 + 1];
            }
        #pragma unroll
        for (int off = 1; off <= 2; off <<= 1)
            #pragma unroll
            for (int mt = 0; mt < 4; mt++) {
                p[mt][0] += __shfl_xor_sync(0xFFFFFFFFu, p[mt][0], off);
                p[mt][1] += __shfl_xor_sync(0xFFFFFFFFu, p[mt][1], off);
            }
        if ((lane & 3) == 0) {
            #pragma unroll
            for (int mt = 0; mt < 4; mt++)
                #pragma unroll
                for (int h = 0; h < 2; h++) {
                    int row = mt * 16 + (lane >> 2) + 8 * h;
                    smf[(OFF_PART >> 2) + row * 8 + w] = p[mt][h];
                }
        }
    }
    __syncthreads();
    if (tid < BM) {
        const float* q = smf + (OFF_PART >> 2) + tid * 8;
        float s = q[0] + q[1] + q[2] + q[3] + q[4] + q[5] + q[6] + q[7];
        out[(size_t)(m0 + tid) * NEXP + c] = s + b3[c];
    }
}

extern "C" void kernel_launch(void* const* d_in, const int* in_sizes, int n_in,
                              void* d_out, int out_size)
{
    const float* st = (const float*)d_in[0];
    const float* W1 = (const float*)d_in[1];
    const float* b1 = (const float*)d_in[2];
    const float* W2 = (const float*)d_in[3];
    const float* b2 = (const float*)d_in[4];
    const float* W3 = (const float*)d_in[5];
    const float* b3 = (const float*)d_in[6];
    float* out = (float*)d_out;

    const int total = NEXP * 8 * 4 * 2 * 128 + NEXP * 8 * 16 * 2 * 128;  // 327680
    convw<<<(total + NTHR - 1) / NTHR, NTHR>>>(W1, W2);

    cudaFuncSetAttribute(moe_disc_mma,
                         cudaFuncAttributeMaxDynamicSharedMemorySize, SMEM_BYTES);
    dim3 grid(65536 / BM, NEXP);
    moe_disc_mma<<<grid, NTHR, SMEM_BYTES>>>(st, b1, b2, W3, b3, out);
}

// round 12
// speedup vs baseline: 1.1245x; 1.0108x over previous
#include <cuda_runtime.h>
#include <cuda_fp16.h>
#include <cstdint>

#define NEXP   8
#define DIM_S  64
#define HID    256
#define BM     64
#define NTHR   128

// Pre-shuffled fp16 B-fragment streams (built by convw each launch).
// Layout: [c][wn][ks][quarter q4=rg*2+nthalf][lane][j(=nt within half)] u32
//   u32 = {W[k][n], W[k+1][n]},  k = ks*16 + (lane&3)*2 + 8*rg,
//   n = wn*64 + nt*8 + (lane>>2),  nt = (q4&1)*4 + j
__device__ uint32_t g_w1s[NEXP * 4 * 4 * 512];    //  65536 u32
__device__ uint32_t g_w2s[NEXP * 4 * 16 * 512];   // 262144 u32

// ---- SMEM (bytes) ----
// A1: fp16 [64 r][64 k], 128 B/row, chunk(16B) swizzle: chunk ^= (row&7)
// H1: fp16 [64 r][256 k], 512 B/row, same swizzle (low 3 chunk bits)
#define OFF_A1    0
#define OFF_H1    8192
#define OFF_B1    40960          // f32[256]
#define OFF_B2    41984
#define OFF_W3    43008
#define OFF_PART  44032          // [64 rows][4 wn] f32
#define SMEM_BYTES 45056

__device__ __forceinline__ uint32_t packh2(float lo, float hi) {
    __half2 h = __floats2half2_rn(lo, hi);
    return *reinterpret_cast<uint32_t*>(&h);
}
__device__ __forceinline__ uint32_t smem_u32(const void* p) {
    uint32_t a;
    asm("{ .reg .u64 t; cvta.to.shared.u64 t, %1; cvt.u32.u64 %0, t; }" : "=r"(a) : "l"(p));
    return a;
}
__device__ __forceinline__ void mma_f16(float c[4], const uint32_t* a,
                                        uint32_t b0, uint32_t b1) {
    asm volatile(
        "mma.sync.aligned.m16n8k16.row.col.f32.f16.f16.f32 "
        "{%0,%1,%2,%3}, {%4,%5,%6,%7}, {%8,%9}, {%0,%1,%2,%3};"
        : "+f"(c[0]), "+f"(c[1]), "+f"(c[2]), "+f"(c[3])
        : "r"(a[0]), "r"(a[1]), "r"(a[2]), "r"(a[3]), "r"(b0), "r"(b1));
}
__device__ __forceinline__ void ldmx4(uint32_t* a, uint32_t addr) {
    asm volatile("ldmatrix.sync.aligned.m8n8.x4.shared.b16 {%0,%1,%2,%3}, [%4];"
        : "=r"(a[0]), "=r"(a[1]), "=r"(a[2]), "=r"(a[3]) : "r"(addr));
}

// Load one ks-step of B fragments (4 coalesced LDG.128).  b[nt*2+rg]
__device__ __forceinline__ void loadBfrag(const uint32_t* __restrict__ bs,
                                          int ks, int lane, uint32_t* b) {
    const uint4* p = reinterpret_cast<const uint4*>(
        bs + (size_t)ks * 512 + lane * 4);
    uint4 v0 = __ldg(p);        // rg0, nt0-3
    uint4 v1 = __ldg(p + 32);   // rg0, nt4-7
    uint4 v2 = __ldg(p + 64);   // rg1, nt0-3
    uint4 v3 = __ldg(p + 96);   // rg1, nt4-7
    b[0]  = v0.x; b[2]  = v0.y; b[4]  = v0.z; b[6]  = v0.w;
    b[8]  = v1.x; b[10] = v1.y; b[12] = v1.z; b[14] = v1.w;
    b[1]  = v2.x; b[3]  = v2.y; b[5]  = v2.z; b[7]  = v2.w;
    b[9]  = v3.x; b[11] = v3.y; b[13] = v3.z; b[15] = v3.w;
}

// ---- prologue: build B-fragment streams from fp32 row-major weights ----
__global__ void __launch_bounds__(256)
convw(const float* __restrict__ W1, const float* __restrict__ W2)
{
    int i = blockIdx.x * 256 + threadIdx.x;
    if (i < NEXP * 4 * 4 * 512) {            // W1 stream
        int j = i & 3, lane = (i >> 2) & 31, q4 = (i >> 7) & 3;
        int ks = (i >> 9) & 3, w = (i >> 11) & 3, c = i >> 13;
        int rg = q4 >> 1, nt = (q4 & 1) * 4 + j;
        int n = w * 64 + nt * 8 + (lane >> 2);
        int k = ks * 16 + (lane & 3) * 2 + rg * 8;
        const float* p = W1 + ((size_t)c * DIM_S + k) * HID + n;
        g_w1s[i] = packh2(p[0], p[HID]);
    } else {
        i -= NEXP * 4 * 4 * 512;
        if (i < NEXP * 4 * 16 * 512) {       // W2 stream
            int j = i & 3, lane = (i >> 2) & 31, q4 = (i >> 7) & 3;
            int ks = (i >> 9) & 15, w = (i >> 13) & 3, c = i >> 15;
            int rg = q4 >> 1, nt = (q4 & 1) * 4 + j;
            int n = w * 64 + nt * 8 + (lane >> 2);
            int k = ks * 16 + (lane & 3) * 2 + rg * 8;
            const float* p = W2 + ((size_t)c * HID + k) * HID + n;
            g_w2s[i] = packh2(p[0], p[HID]);
        }
    }
}

// GEMM: acc[4][8][4] += A(rows 0..63, K = TOT16*16, smem swizzled row-major
// fp16, ROWB bytes/row) * B(fragment stream, this warp's 64 cols).
// breg[0], breg[1] preloaded by caller (ks = 0, 1).
template<int TOT16, int ROWB>
__device__ __forceinline__ void gemm(const uint32_t* __restrict__ bs,
                                     uint32_t afb, float acc[4][8][4],
                                     int lane, uint32_t breg[3][16])
{
    const int arow = ((lane >> 3) & 1) * 8 + (lane & 7);
    const int jj   = lane >> 4;
    const uint32_t abase = afb + arow * ROWB;
    const int      amask = arow & 7;

    uint32_t areg[2][4];

    auto loadA = [&](int ks, int mt, uint32_t* a) {
        int chunk = (2 * ks + jj) ^ amask;
        ldmx4(a, abase + mt * 16 * ROWB + chunk * 16);
    };

    loadA(0, 0, areg[0]);

    #pragma unroll
    for (int ks = 0; ks < TOT16; ks++) {
        if (ks + 2 < TOT16) loadBfrag(bs, ks + 2, lane, breg[(ks + 2) % 3]);
        const uint32_t* b = breg[ks % 3];
        #pragma unroll
        for (int mt = 0; mt < 4; mt++) {
            if (!(mt == 3 && ks + 1 == TOT16))
                loadA(mt == 3 ? ks + 1 : ks, (mt + 1) & 3, areg[(mt + 1) & 1]);
            const uint32_t* a = areg[mt & 1];
            #pragma unroll
            for (int nt = 0; nt < 8; nt++)
                mma_f16(acc[mt][nt], a, b[nt * 2], b[nt * 2 + 1]);
        }
    }
}

__global__ void __launch_bounds__(NTHR, 2)
moe_disc_mma(const float* __restrict__ st,
             const float* __restrict__ b1, const float* __restrict__ b2,
             const float* __restrict__ W3, const float* __restrict__ b3,
             float* __restrict__ out)
{
    extern __shared__ char smem[];
    float* smf = reinterpret_cast<float*>(smem);
    const uint32_t sb = smem_u32(smem);
    const int tid  = threadIdx.x;
    const int wn   = tid >> 5;        // 0..3 : 64-col block
    const int lane = tid & 31;
    const int c    = blockIdx.y;
    const int m0   = blockIdx.x * BM;

    const uint32_t* bs1 = g_w1s + ((size_t)(c * 4 + wn)) * 2048;
    const uint32_t* bs2 = g_w2s + ((size_t)(c * 4 + wn)) * 8192;

    // GEMM1's first two B k-steps fly under staging
    uint32_t breg[3][16];
    loadBfrag(bs1, 0, lane, breg[0]);
    loadBfrag(bs1, 1, lane, breg[1]);

    // ---- stage biases / w3 / A1 ----
    smf[(OFF_B1 >> 2) + tid] = b1[c * HID + tid];
    smf[(OFF_B1 >> 2) + 128 + tid] = b1[c * HID + 128 + tid];
    smf[(OFF_B2 >> 2) + tid] = b2[c * HID + tid];
    smf[(OFF_B2 >> 2) + 128 + tid] = b2[c * HID + 128 + tid];
    smf[(OFF_W3 >> 2) + tid] = W3[c * HID + tid];
    smf[(OFF_W3 >> 2) + 128 + tid] = W3[c * HID + 128 + tid];

    #pragma unroll
    for (int i = 0; i < 8; i++) {
        int idx = tid + i * NTHR;       // 0..1023 float4
        int row = idx >> 4, f4 = idx & 15;
        float4 v = *reinterpret_cast<const float4*>(
            st + (size_t)(m0 + row) * DIM_S + f4 * 4);
        uint32_t byte = OFF_A1 + row * 128
                      + (uint32_t)(((f4 >> 1) ^ (row & 7)) * 16 + 8 * (f4 & 1));
        *reinterpret_cast<uint2*>(smem + byte) =
            make_uint2(packh2(v.x, v.y), packh2(v.z, v.w));
    }
    __syncthreads();

    float acc[4][8][4];
    #pragma unroll
    for (int a = 0; a < 4; a++)
        #pragma unroll
        for (int b = 0; b < 8; b++)
            #pragma unroll
            for (int e = 0; e < 4; e++) acc[a][b][e] = 0.f;

    // ---- layer 1 GEMM (K = 64) ----
    gemm<4, 128>(bs1, sb + OFF_A1, acc, lane, breg);

    // GEMM2's first two B k-steps fly under epilogue 1
    loadBfrag(bs2, 0, lane, breg[0]);
    loadBfrag(bs2, 1, lane, breg[1]);

    // ---- epilogue 1: H1 = fp16(relu(acc + b1)), swizzled row-major ----
    // phys col of acc[mt][nt][reg] = wn*64 + nt*8 + 2*(lane&3) + (reg&1)
    {
        float b1v[16];
        #pragma unroll
        for (int nt = 0; nt < 8; nt++) {
            int k0 = wn * 64 + nt * 8 + 2 * (lane & 3);
            b1v[nt * 2]     = smf[(OFF_B1 >> 2) + k0];
            b1v[nt * 2 + 1] = smf[(OFF_B1 >> 2) + k0 + 1];
        }
        #pragma unroll
        for (int mt = 0; mt < 4; mt++)
            #pragma unroll
            for (int nt = 0; nt < 8; nt++) {
                int r0 = mt * 16 + (lane >> 2);
                int chunk = wn * 8 + nt;
                uint32_t p0 = packh2(
                    fmaxf(acc[mt][nt][0] + b1v[nt * 2], 0.f),
                    fmaxf(acc[mt][nt][1] + b1v[nt * 2 + 1], 0.f));
                uint32_t p1 = packh2(
                    fmaxf(acc[mt][nt][2] + b1v[nt * 2], 0.f),
                    fmaxf(acc[mt][nt][3] + b1v[nt * 2 + 1], 0.f));
                uint32_t by0 = OFF_H1 + r0 * 512
                             + ((chunk ^ (r0 & 7)) * 16) + 4 * (lane & 3);
                int r1 = r0 + 8;
                uint32_t by1 = OFF_H1 + r1 * 512
                             + ((chunk ^ (r1 & 7)) * 16) + 4 * (lane & 3);
                *reinterpret_cast<uint32_t*>(smem + by0) = p0;
                *reinterpret_cast<uint32_t*>(smem + by1) = p1;
            }
    }
    #pragma unroll
    for (int a = 0; a < 4; a++)
        #pragma unroll
        for (int b = 0; b < 8; b++)
            #pragma unroll
            for (int e = 0; e < 4; e++) acc[a][b][e] = 0.f;

    __syncthreads();   // H1 visible

    // ---- layer 2 GEMM (K = 256) ----
    gemm<16, 512>(bs2, sb + OFF_H1, acc, lane, breg);

    // ---- epilogue 2: d = relu(acc + b2) . w3, reduce, + b3 ----
    {
        float b2v[16], w3v[16];
        #pragma unroll
        for (int nt = 0; nt < 8; nt++) {
            int k0 = wn * 64 + nt * 8 + 2 * (lane & 3);
            b2v[nt * 2]     = smf[(OFF_B2 >> 2) + k0];
            b2v[nt * 2 + 1] = smf[(OFF_B2 >> 2) + k0 + 1];
            w3v[nt * 2]     = smf[(OFF_W3 >> 2) + k0];
            w3v[nt * 2 + 1] = smf[(OFF_W3 >> 2) + k0 + 1];
        }
        float p[4][2];
        #pragma unroll
        for (int mt = 0; mt < 4; mt++) { p[mt][0] = 0.f; p[mt][1] = 0.f; }
        #pragma unroll
        for (int mt = 0; mt < 4; mt++)
            #pragma unroll
            for (int nt = 0; nt < 8; nt++) {
                p[mt][0] += fmaxf(acc[mt][nt][0] + b2v[nt * 2], 0.f)     * w3v[nt * 2]
                          + fmaxf(acc[mt][nt][1] + b2v[nt * 2 + 1], 0.f) * w3v[nt * 2 + 1];
                p[mt][1] += fmaxf(acc[mt][nt][2] + b2v[nt * 2], 0.f)     * w3v[nt * 2]
                          + fmaxf(acc[mt][nt][3] + b2v[nt * 2 + 1], 0.f) * w3v[nt * 2 + 1];
            }
        #pragma unroll
        for (int off = 1; off <= 2; off <<= 1)
            #pragma unroll
            for (int mt = 0; mt < 4; mt++) {
                p[mt][0] += __shfl_xor_sync(0xFFFFFFFFu, p[mt][0], off);
                p[mt][1] += __shfl_xor_sync(0xFFFFFFFFu, p[mt][1], off);
            }
        if ((lane & 3) == 0) {
            #pragma unroll
            for (int mt = 0; mt < 4; mt++)
                #pragma unroll
                for (int h = 0; h < 2; h++) {
                    int row = mt * 16 + (lane >> 2) + 8 * h;
                    smf[(OFF_PART >> 2) + row * 4 + wn] = p[mt][h];
                }
        }
    }
    __syncthreads();
    if (tid < BM) {
        const float* q = smf + (OFF_PART >> 2) + tid * 4;
        out[(size_t)(m0 + tid) * NEXP + c] = q[0] + q[1] + q[2] + q[3] + b3[c];
    }
}

extern "C" void kernel_launch(void* const* d_in, const int* in_sizes, int n_in,
                              void* d_out, int out_size)
{
    const float* st = (const float*)d_in[0];
    const float* W1 = (const float*)d_in[1];
    const float* b1 = (const float*)d_in[2];
    const float* W2 = (const float*)d_in[3];
    const float* b2 = (const float*)d_in[4];
    const float* W3 = (const float*)d_in[5];
    const float* b3 = (const float*)d_in[6];
    float* out = (float*)d_out;

    const int total = NEXP * 4 * 4 * 512 + NEXP * 4 * 16 * 512;  // 327680
    convw<<<(total + 255) / 256, 256>>>(W1, W2);

    cudaFuncSetAttribute(moe_disc_mma,
                         cudaFuncAttributeMaxDynamicSharedMemorySize, SMEM_BYTES);
    dim3 grid(65536 / BM, NEXP);
    moe_disc_mma<<<grid, NTHR, SMEM_BYTES>>>(st, b1, b2, W3, b3, out);
}

// round 13
// speedup vs baseline: 1.1865x; 1.0551x over previous
#include <cuda_runtime.h>
#include <cuda_fp16.h>
#include <cstdint>

#define NEXP   8
#define DIM_S  64
#define HID    256
#define BM     64
#define NTHR   128

// Pre-shuffled fp16 B-fragment streams (built by convw each launch).
// Layout: [c][wn][ks][quarter q4=rg*2+nthalf][lane][j(=nt within half)] u32
//   u32 = {W[k][n], W[k+1][n]},  k = ks*16 + (lane&3)*2 + 8*rg,
//   n = wn*64 + nt*8 + (lane>>2),  nt = (q4&1)*4 + j
__device__ uint32_t g_w1s[NEXP * 4 * 4 * 512];    //  65536 u32
__device__ uint32_t g_w2s[NEXP * 4 * 16 * 512];   // 262144 u32

// ---- SMEM (bytes) ----
// A1: fp16 [64 r][64 k], 128 B/row, chunk(16B) swizzle: chunk ^= (row&7)
// H1: fp16 [64 r][256 k], 512 B/row, same swizzle (low 3 chunk bits)
#define OFF_A1    0
#define OFF_H1    8192
#define OFF_B1    40960          // u32[128]: b1 as half2 col-pairs
#define OFF_B2    41472          // f32[256]
#define OFF_W3    42496          // f32[256]
#define OFF_PART  43520          // [64 rows][4 wn] f32
#define SMEM_BYTES 44544

__device__ __forceinline__ uint32_t packh2(float lo, float hi) {
    __half2 h = __floats2half2_rn(lo, hi);
    return *reinterpret_cast<uint32_t*>(&h);
}
__device__ __forceinline__ uint32_t smem_u32(const void* p) {
    uint32_t a;
    asm("{ .reg .u64 t; cvta.to.shared.u64 t, %1; cvt.u32.u64 %0, t; }" : "=r"(a) : "l"(p));
    return a;
}
// f16-accumulate MMA: C/D are 2 x f16x2 regs.
__device__ __forceinline__ void mma_h(uint32_t c[2], const uint32_t* a,
                                      uint32_t b0, uint32_t b1) {
    asm volatile(
        "mma.sync.aligned.m16n8k16.row.col.f16.f16.f16.f16 "
        "{%0,%1}, {%2,%3,%4,%5}, {%6,%7}, {%0,%1};"
        : "+r"(c[0]), "+r"(c[1])
        : "r"(a[0]), "r"(a[1]), "r"(a[2]), "r"(a[3]), "r"(b0), "r"(b1));
}
__device__ __forceinline__ void ldmx4(uint32_t* a, uint32_t addr) {
    asm volatile("ldmatrix.sync.aligned.m8n8.x4.shared.b16 {%0,%1,%2,%3}, [%4];"
        : "=r"(a[0]), "=r"(a[1]), "=r"(a[2]), "=r"(a[3]) : "r"(addr));
}
__device__ __forceinline__ uint32_t hadd2u(uint32_t x, uint32_t y) {
    __half2 r = __hadd2(*reinterpret_cast<__half2*>(&x),
                        *reinterpret_cast<__half2*>(&y));
    return *reinterpret_cast<uint32_t*>(&r);
}
__device__ __forceinline__ uint32_t hmax2z(uint32_t x) {
    __half2 z = __float2half2_rn(0.f);
    __half2 r = __hmax2(*reinterpret_cast<__half2*>(&x), z);
    return *reinterpret_cast<uint32_t*>(&r);
}

// Load one ks-step of B fragments (4 coalesced LDG.128).  b[nt*2+rg]
__device__ __forceinline__ void loadBfrag(const uint32_t* __restrict__ bs,
                                          int ks, int lane, uint32_t* b) {
    const uint4* p = reinterpret_cast<const uint4*>(
        bs + (size_t)ks * 512 + lane * 4);
    uint4 v0 = __ldg(p);        // rg0, nt0-3
    uint4 v1 = __ldg(p + 32);   // rg0, nt4-7
    uint4 v2 = __ldg(p + 64);   // rg1, nt0-3
    uint4 v3 = __ldg(p + 96);   // rg1, nt4-7
    b[0]  = v0.x; b[2]  = v0.y; b[4]  = v0.z; b[6]  = v0.w;
    b[8]  = v1.x; b[10] = v1.y; b[12] = v1.z; b[14] = v1.w;
    b[1]  = v2.x; b[3]  = v2.y; b[5]  = v2.z; b[7]  = v2.w;
    b[9]  = v3.x; b[11] = v3.y; b[13] = v3.z; b[15] = v3.w;
}

// ---- prologue: build B-fragment streams from fp32 row-major weights ----
__global__ void __launch_bounds__(256)
convw(const float* __restrict__ W1, const float* __restrict__ W2)
{
    int i = blockIdx.x * 256 + threadIdx.x;
    if (i < NEXP * 4 * 4 * 512) {            // W1 stream
        int j = i & 3, lane = (i >> 2) & 31, q4 = (i >> 7) & 3;
        int ks = (i >> 9) & 3, w = (i >> 11) & 3, c = i >> 13;
        int rg = q4 >> 1, nt = (q4 & 1) * 4 + j;
        int n = w * 64 + nt * 8 + (lane >> 2);
        int k = ks * 16 + (lane & 3) * 2 + rg * 8;
        const float* p = W1 + ((size_t)c * DIM_S + k) * HID + n;
        g_w1s[i] = packh2(p[0], p[HID]);
    } else {
        i -= NEXP * 4 * 4 * 512;
        if (i < NEXP * 4 * 16 * 512) {       // W2 stream
            int j = i & 3, lane = (i >> 2) & 31, q4 = (i >> 7) & 3;
            int ks = (i >> 9) & 15, w = (i >> 13) & 3, c = i >> 15;
            int rg = q4 >> 1, nt = (q4 & 1) * 4 + j;
            int n = w * 64 + nt * 8 + (lane >> 2);
            int k = ks * 16 + (lane & 3) * 2 + rg * 8;
            const float* p = W2 + ((size_t)c * HID + k) * HID + n;
            g_w2s[i] = packh2(p[0], p[HID]);
        }
    }
}

// GEMM (f16 acc): ks < SPLIT accumulates into accA, ks >= SPLIT into accB.
// A rows 0..63, K = TOT16*16, smem swizzled row-major fp16, ROWB bytes/row.
// breg[0], breg[1] preloaded by caller (ks = 0, 1).
template<int TOT16, int SPLIT, int ROWB>
__device__ __forceinline__ void gemm(const uint32_t* __restrict__ bs,
                                     uint32_t afb,
                                     uint32_t accA[4][8][2],
                                     uint32_t accB[4][8][2],
                                     int lane, uint32_t breg[3][16])
{
    const int arow = ((lane >> 3) & 1) * 8 + (lane & 7);
    const int jj   = lane >> 4;
    const uint32_t abase = afb + arow * ROWB;
    const int      amask = arow & 7;

    uint32_t areg[2][4];

    auto loadA = [&](int ks, int mt, uint32_t* a) {
        int chunk = (2 * ks + jj) ^ amask;
        ldmx4(a, abase + mt * 16 * ROWB + chunk * 16);
    };

    loadA(0, 0, areg[0]);

    #pragma unroll
    for (int ks = 0; ks < TOT16; ks++) {
        if (ks + 2 < TOT16) loadBfrag(bs, ks + 2, lane, breg[(ks + 2) % 3]);
        const uint32_t* b = breg[ks % 3];
        #pragma unroll
        for (int mt = 0; mt < 4; mt++) {
            if (!(mt == 3 && ks + 1 == TOT16))
                loadA(mt == 3 ? ks + 1 : ks, (mt + 1) & 3, areg[(mt + 1) & 1]);
            const uint32_t* a = areg[mt & 1];
            #pragma unroll
            for (int nt = 0; nt < 8; nt++)
                mma_h(ks < SPLIT ? accA[mt][nt] : accB[mt][nt],
                      a, b[nt * 2], b[nt * 2 + 1]);
        }
    }
}

__global__ void __launch_bounds__(NTHR, 2)
moe_disc_mma(const float* __restrict__ st,
             const float* __restrict__ b1, const float* __restrict__ b2,
             const float* __restrict__ W3, const float* __restrict__ b3,
             float* __restrict__ out)
{
    extern __shared__ char smem[];
    float* smf = reinterpret_cast<float*>(smem);
    uint32_t* smu = reinterpret_cast<uint32_t*>(smem);
    const uint32_t sb = smem_u32(smem);
    const int tid  = threadIdx.x;
    const int wn   = tid >> 5;        // 0..3 : 64-col block
    const int lane = tid & 31;
    const int c    = blockIdx.y;
    const int m0   = blockIdx.x * BM;

    const uint32_t* bs1 = g_w1s + ((size_t)(c * 4 + wn)) * 2048;
    const uint32_t* bs2 = g_w2s + ((size_t)(c * 4 + wn)) * 8192;

    // GEMM1's first two B k-steps fly under staging
    uint32_t breg[3][16];
    loadBfrag(bs1, 0, lane, breg[0]);
    loadBfrag(bs1, 1, lane, breg[1]);

    // ---- stage b1 (half2 pairs), b2/w3 (f32), A1 ----
    smu[(OFF_B1 >> 2) + tid] = packh2(b1[c * HID + 2 * tid],
                                      b1[c * HID + 2 * tid + 1]);
    smf[(OFF_B2 >> 2) + tid] = b2[c * HID + tid];
    smf[(OFF_B2 >> 2) + 128 + tid] = b2[c * HID + 128 + tid];
    smf[(OFF_W3 >> 2) + tid] = W3[c * HID + tid];
    smf[(OFF_W3 >> 2) + 128 + tid] = W3[c * HID + 128 + tid];

    #pragma unroll
    for (int i = 0; i < 8; i++) {
        int idx = tid + i * NTHR;       // 0..1023 float4
        int row = idx >> 4, f4 = idx & 15;
        float4 v = *reinterpret_cast<const float4*>(
            st + (size_t)(m0 + row) * DIM_S + f4 * 4);
        uint32_t byte = OFF_A1 + row * 128
                      + (uint32_t)(((f4 >> 1) ^ (row & 7)) * 16 + 8 * (f4 & 1));
        *reinterpret_cast<uint2*>(smem + byte) =
            make_uint2(packh2(v.x, v.y), packh2(v.z, v.w));
    }
    __syncthreads();

    uint32_t accA[4][8][2], accB[4][8][2];
    #pragma unroll
    for (int a = 0; a < 4; a++)
        #pragma unroll
        for (int b = 0; b < 8; b++) {
            accA[a][b][0] = 0u; accA[a][b][1] = 0u;
        }

    // ---- layer 1 GEMM (K = 64, single f16 chain into accA) ----
    gemm<4, 8, 128>(bs1, sb + OFF_A1, accA, accB, lane, breg);

    // GEMM2's first two B k-steps fly under epilogue 1
    loadBfrag(bs2, 0, lane, breg[0]);
    loadBfrag(bs2, 1, lane, breg[1]);

    // ---- epilogue 1: H1 = hmax2(accA + b1h2, 0), direct half2 STS ----
    // phys col pair of accA[mt][nt][r2] = wn*64 + nt*8 + 2*(lane&3)
    {
        uint32_t b1p[8];
        #pragma unroll
        for (int nt = 0; nt < 8; nt++)
            b1p[nt] = smu[(OFF_B1 >> 2) + wn * 32 + nt * 4 + (lane & 3)];
        #pragma unroll
        for (int mt = 0; mt < 4; mt++)
            #pragma unroll
            for (int nt = 0; nt < 8; nt++) {
                int r0 = mt * 16 + (lane >> 2);
                int chunk = wn * 8 + nt;
                uint32_t p0 = hmax2z(hadd2u(accA[mt][nt][0], b1p[nt]));
                uint32_t p1 = hmax2z(hadd2u(accA[mt][nt][1], b1p[nt]));
                uint32_t by0 = OFF_H1 + r0 * 512
                             + ((chunk ^ (r0 & 7)) * 16) + 4 * (lane & 3);
                int r1 = r0 + 8;
                uint32_t by1 = OFF_H1 + r1 * 512
                             + ((chunk ^ (r1 & 7)) * 16) + 4 * (lane & 3);
                *reinterpret_cast<uint32_t*>(smem + by0) = p0;
                *reinterpret_cast<uint32_t*>(smem + by1) = p1;
            }
    }
    #pragma unroll
    for (int a = 0; a < 4; a++)
        #pragma unroll
        for (int b = 0; b < 8; b++) {
            accA[a][b][0] = 0u; accA[a][b][1] = 0u;
            accB[a][b][0] = 0u; accB[a][b][1] = 0u;
        }

    __syncthreads();   // H1 visible

    // ---- layer 2 GEMM (K = 256): two 8-step f16 chains (accA, accB) ----
    gemm<16, 8, 512>(bs2, sb + OFF_H1, accA, accB, lane, breg);

    // ---- epilogue 2: combine chains in f32, relu+dot w3, reduce, +b3 ----
    {
        float b2v[16], w3v[16];
        #pragma unroll
        for (int nt = 0; nt < 8; nt++) {
            int k0 = wn * 64 + nt * 8 + 2 * (lane & 3);
            b2v[nt * 2]     = smf[(OFF_B2 >> 2) + k0];
            b2v[nt * 2 + 1] = smf[(OFF_B2 >> 2) + k0 + 1];
            w3v[nt * 2]     = smf[(OFF_W3 >> 2) + k0];
            w3v[nt * 2 + 1] = smf[(OFF_W3 >> 2) + k0 + 1];
        }
        float p[4][2];
        #pragma unroll
        for (int mt = 0; mt < 4; mt++) { p[mt][0] = 0.f; p[mt][1] = 0.f; }
        #pragma unroll
        for (int mt = 0; mt < 4; mt++)
            #pragma unroll
            for (int nt = 0; nt < 8; nt++)
                #pragma unroll
                for (int r2 = 0; r2 < 2; r2++) {
                    float2 fa = __half22float2(
                        *reinterpret_cast<__half2*>(&accA[mt][nt][r2]));
                    float2 fb = __half22float2(
                        *reinterpret_cast<__half2*>(&accB[mt][nt][r2]));
                    float v0 = fa.x + fb.x, v1 = fa.y + fb.y;
                    p[mt][r2] += fmaxf(v0 + b2v[nt * 2], 0.f)     * w3v[nt * 2]
                               + fmaxf(v1 + b2v[nt * 2 + 1], 0.f) * w3v[nt * 2 + 1];
                }
        #pragma unroll
        for (int off = 1; off <= 2; off <<= 1)
            #pragma unroll
            for (int mt = 0; mt < 4; mt++) {
                p[mt][0] += __shfl_xor_sync(0xFFFFFFFFu, p[mt][0], off);
                p[mt][1] += __shfl_xor_sync(0xFFFFFFFFu, p[mt][1], off);
            }
        if ((lane & 3) == 0) {
            #pragma unroll
            for (int mt = 0; mt < 4; mt++)
                #pragma unroll
                for (int h = 0; h < 2; h++) {
                    int row = mt * 16 + (lane >> 2) + 8 * h;
                    smf[(OFF_PART >> 2) + row * 4 + wn] = p[mt][h];
                }
        }
    }
    __syncthreads();
    if (tid < BM) {
        const float* q = smf + (OFF_PART >> 2) + tid * 4;
        out[(size_t)(m0 + tid) * NEXP + c] = q[0] + q[1] + q[2] + q[3] + b3[c];
    }
}

extern "C" void kernel_launch(void* const* d_in, const int* in_sizes, int n_in,
                              void* d_out, int out_size)
{
    const float* st = (const float*)d_in[0];
    const float* W1 = (const float*)d_in[1];
    const float* b1 = (const float*)d_in[2];
    const float* W2 = (const float*)d_in[3];
    const float* b2 = (const float*)d_in[4];
    const float* W3 = (const float*)d_in[5];
    const float* b3 = (const float*)d_in[6];
    float* out = (float*)d_out;

    const int total = NEXP * 4 * 4 * 512 + NEXP * 4 * 16 * 512;  // 327680
    convw<<<(total + 255) / 256, 256>>>(W1, W2);

    cudaFuncSetAttribute(moe_disc_mma,
                         cudaFuncAttributeMaxDynamicSharedMemorySize, SMEM_BYTES);
    dim3 grid(65536 / BM, NEXP);
    moe_disc_mma<<<grid, NTHR, SMEM_BYTES>>>(st, b1, b2, W3, b3, out);
}

// round 14
// speedup vs baseline: 1.2194x; 1.0278x over previous
#include <cuda_runtime.h>
#include <cuda_fp16.h>
#include <cstdint>

#define NEXP   8
#define DIM_S  64
#define HID    256
#define BM     64
#define NTHR   128

// Pre-shuffled fp16 B-fragment streams (built by convw each launch).
// Layout: [c][wn][ks][quarter q4=rg*2+nthalf][lane][j(=nt within half)] u32
//   u32 = {W[k][n], W[k+1][n]},  k = ks*16 + (lane&3)*2 + 8*rg,
//   n = wn*64 + nt*8 + (lane>>2),  nt = (q4&1)*4 + j
__device__ uint32_t g_w1s[NEXP * 4 * 4 * 512];    //  65536 u32
__device__ uint32_t g_w2s[NEXP * 4 * 16 * 512];   // 262144 u32

// ---- SMEM (bytes) ----
// A1: fp16 [64 r][64 k], 128 B/row, chunk(16B) swizzle: chunk ^= (row&7)
// H1: fp16 [64 r][256 k], 512 B/row, same swizzle (low 3 chunk bits)
#define OFF_A1    0
#define OFF_H1    8192
#define OFF_B1    40960          // u32[128]: b1 as half2 col-pairs
#define OFF_B2    41472          // u32[128]: b2 as half2 col-pairs
#define OFF_W3    41984          // u32[128]: w3 as half2 col-pairs
#define OFF_PART  42496          // [64 rows][4 wn] f32
#define SMEM_BYTES 43520

__device__ __forceinline__ uint32_t packh2(float lo, float hi) {
    __half2 h = __floats2half2_rn(lo, hi);
    return *reinterpret_cast<uint32_t*>(&h);
}
__device__ __forceinline__ __half2 u2h(uint32_t x) {
    return *reinterpret_cast<__half2*>(&x);
}
__device__ __forceinline__ uint32_t smem_u32(const void* p) {
    uint32_t a;
    asm("{ .reg .u64 t; cvta.to.shared.u64 t, %1; cvt.u32.u64 %0, t; }" : "=r"(a) : "l"(p));
    return a;
}
// f16-accumulate MMA: C/D are 2 x f16x2 regs.
__device__ __forceinline__ void mma_h(uint32_t c[2], const uint32_t* a,
                                      uint32_t b0, uint32_t b1) {
    asm volatile(
        "mma.sync.aligned.m16n8k16.row.col.f16.f16.f16.f16 "
        "{%0,%1}, {%2,%3,%4,%5}, {%6,%7}, {%0,%1};"
        : "+r"(c[0]), "+r"(c[1])
        : "r"(a[0]), "r"(a[1]), "r"(a[2]), "r"(a[3]), "r"(b0), "r"(b1));
}
__device__ __forceinline__ void ldmx4(uint32_t* a, uint32_t addr) {
    asm volatile("ldmatrix.sync.aligned.m8n8.x4.shared.b16 {%0,%1,%2,%3}, [%4];"
        : "=r"(a[0]), "=r"(a[1]), "=r"(a[2]), "=r"(a[3]) : "r"(addr));
}
__device__ __forceinline__ uint32_t hadd2u(uint32_t x, uint32_t y) {
    __half2 r = __hadd2(u2h(x), u2h(y));
    return *reinterpret_cast<uint32_t*>(&r);
}
__device__ __forceinline__ uint32_t hmax2z(uint32_t x) {
    __half2 z = __float2half2_rn(0.f);
    __half2 r = __hmax2(u2h(x), z);
    return *reinterpret_cast<uint32_t*>(&r);
}

// Load one ks-step of B fragments from a pre-offset uint4 pointer.
__device__ __forceinline__ void loadBfrag(const uint4* __restrict__ p,
                                          uint32_t* b) {
    uint4 v0 = __ldg(p);        // rg0, nt0-3
    uint4 v1 = __ldg(p + 32);   // rg0, nt4-7
    uint4 v2 = __ldg(p + 64);   // rg1, nt0-3
    uint4 v3 = __ldg(p + 96);   // rg1, nt4-7
    b[0]  = v0.x; b[2]  = v0.y; b[4]  = v0.z; b[6]  = v0.w;
    b[8]  = v1.x; b[10] = v1.y; b[12] = v1.z; b[14] = v1.w;
    b[1]  = v2.x; b[3]  = v2.y; b[5]  = v2.z; b[7]  = v2.w;
    b[9]  = v3.x; b[11] = v3.y; b[13] = v3.z; b[15] = v3.w;
}

// ---- prologue: build B-fragment streams from fp32 row-major weights ----
__global__ void __launch_bounds__(256)
convw(const float* __restrict__ W1, const float* __restrict__ W2)
{
    int i = blockIdx.x * 256 + threadIdx.x;
    if (i < NEXP * 4 * 4 * 512) {            // W1 stream
        int j = i & 3, lane = (i >> 2) & 31, q4 = (i >> 7) & 3;
        int ks = (i >> 9) & 3, w = (i >> 11) & 3, c = i >> 13;
        int rg = q4 >> 1, nt = (q4 & 1) * 4 + j;
        int n = w * 64 + nt * 8 + (lane >> 2);
        int k = ks * 16 + (lane & 3) * 2 + rg * 8;
        const float* p = W1 + ((size_t)c * DIM_S + k) * HID + n;
        g_w1s[i] = packh2(p[0], p[HID]);
    } else {
        i -= NEXP * 4 * 4 * 512;
        if (i < NEXP * 4 * 16 * 512) {       // W2 stream
            int j = i & 3, lane = (i >> 2) & 31, q4 = (i >> 7) & 3;
            int ks = (i >> 9) & 15, w = (i >> 13) & 3, c = i >> 15;
            int rg = q4 >> 1, nt = (q4 & 1) * 4 + j;
            int n = w * 64 + nt * 8 + (lane >> 2);
            int k = ks * 16 + (lane & 3) * 2 + rg * 8;
            const float* p = W2 + ((size_t)c * HID + k) * HID + n;
            g_w2s[i] = packh2(p[0], p[HID]);
        }
    }
}

// GEMM (f16 acc): ks < SPLIT accumulates into accA, ks >= SPLIT into accB.
// A rows 0..63, K = TOT16*16, smem swizzled row-major fp16, ROWB bytes/row.
// pb = (const uint4*)bstream + lane; breg[0], breg[1] preloaded (ks = 0, 1).
template<int TOT16, int SPLIT, int ROWB>
__device__ __forceinline__ void gemm(const uint4* __restrict__ pb,
                                     uint32_t afb,
                                     uint32_t accA[4][8][2],
                                     uint32_t accB[4][8][2],
                                     int lane, uint32_t breg[3][16])
{
    const int arow = ((lane >> 3) & 1) * 8 + (lane & 7);
    const int jj   = lane >> 4;
    const uint32_t abase = afb + arow * ROWB;
    const int      amask = arow & 7;

    uint32_t areg[2][4];

    auto loadA = [&](int ks, int mt, uint32_t* a) {
        int chunk = (2 * ks + jj) ^ amask;
        ldmx4(a, abase + mt * 16 * ROWB + chunk * 16);
    };

    loadA(0, 0, areg[0]);

    const uint4* pf = pb + 2 * 128;   // prefetch pointer (ks+2)

    #pragma unroll
    for (int ks = 0; ks < TOT16; ks++) {
        if (ks + 2 < TOT16) { loadBfrag(pf, breg[(ks + 2) % 3]); pf += 128; }
        const uint32_t* b = breg[ks % 3];
        #pragma unroll
        for (int mt = 0; mt < 4; mt++) {
            if (!(mt == 3 && ks + 1 == TOT16))
                loadA(mt == 3 ? ks + 1 : ks, (mt + 1) & 3, areg[(mt + 1) & 1]);
            const uint32_t* a = areg[mt & 1];
            #pragma unroll
            for (int nt = 0; nt < 8; nt++)
                mma_h(ks < SPLIT ? accA[mt][nt] : accB[mt][nt],
                      a, b[nt * 2], b[nt * 2 + 1]);
        }
    }
}

__global__ void __launch_bounds__(NTHR, 2)
moe_disc_mma(const float* __restrict__ st,
             const float* __restrict__ b1, const float* __restrict__ b2,
             const float* __restrict__ W3, const float* __restrict__ b3,
             float* __restrict__ out)
{
    extern __shared__ char smem[];
    float* smf = reinterpret_cast<float*>(smem);
    uint32_t* smu = reinterpret_cast<uint32_t*>(smem);
    const uint32_t sb = smem_u32(smem);
    const int tid  = threadIdx.x;
    const int wn   = tid >> 5;        // 0..3 : 64-col block
    const int lane = tid & 31;
    const int c    = blockIdx.y;
    const int m0   = blockIdx.x * BM;

    const uint4* pb1 = reinterpret_cast<const uint4*>(
        g_w1s + ((size_t)(c * 4 + wn)) * 2048) + lane;
    const uint4* pb2 = reinterpret_cast<const uint4*>(
        g_w2s + ((size_t)(c * 4 + wn)) * 8192) + lane;

    // GEMM1's first two B k-steps fly under staging
    uint32_t breg[3][16];
    loadBfrag(pb1, breg[0]);
    loadBfrag(pb1 + 128, breg[1]);

    // ---- stage b1/b2/w3 as half2 col-pairs, and A1 ----
    {
        float2 v1 = *reinterpret_cast<const float2*>(b1 + c * HID + 2 * tid);
        float2 v2 = *reinterpret_cast<const float2*>(b2 + c * HID + 2 * tid);
        float2 v3 = *reinterpret_cast<const float2*>(W3 + c * HID + 2 * tid);
        smu[(OFF_B1 >> 2) + tid] = packh2(v1.x, v1.y);
        smu[(OFF_B2 >> 2) + tid] = packh2(v2.x, v2.y);
        smu[(OFF_W3 >> 2) + tid] = packh2(v3.x, v3.y);
    }

    #pragma unroll
    for (int i = 0; i < 8; i++) {
        int idx = tid + i * NTHR;       // 0..1023 float4
        int row = idx >> 4, f4 = idx & 15;
        float4 v = *reinterpret_cast<const float4*>(
            st + (size_t)(m0 + row) * DIM_S + f4 * 4);
        uint32_t byte = OFF_A1 + row * 128
                      + (uint32_t)(((f4 >> 1) ^ (row & 7)) * 16 + 8 * (f4 & 1));
        *reinterpret_cast<uint2*>(smem + byte) =
            make_uint2(packh2(v.x, v.y), packh2(v.z, v.w));
    }
    __syncthreads();

    uint32_t accA[4][8][2], accB[4][8][2];
    #pragma unroll
    for (int a = 0; a < 4; a++)
        #pragma unroll
        for (int b = 0; b < 8; b++) {
            accA[a][b][0] = 0u; accA[a][b][1] = 0u;
        }

    // ---- layer 1 GEMM (K = 64, single f16 chain into accA) ----
    gemm<4, 8, 128>(pb1, sb + OFF_A1, accA, accB, lane, breg);

    // GEMM2's first two B k-steps fly under epilogue 1
    loadBfrag(pb2, breg[0]);
    loadBfrag(pb2 + 128, breg[1]);

    // ---- epilogue 1: H1 = hmax2(accA + b1h2, 0), direct half2 STS ----
    // phys col pair of accA[mt][nt][r2] = wn*64 + nt*8 + 2*(lane&3)
    {
        uint32_t b1p[8];
        #pragma unroll
        for (int nt = 0; nt < 8; nt++)
            b1p[nt] = smu[(OFF_B1 >> 2) + wn * 32 + nt * 4 + (lane & 3)];
        const int c0 = (lane >> 2) & 7;
        const uint32_t eb = OFF_H1 + (lane >> 2) * 512 + wn * 128
                          + 4 * (lane & 3);
        #pragma unroll
        for (int mt = 0; mt < 4; mt++) {
            const uint32_t ebm = eb + mt * 8192;
            #pragma unroll
            for (int nt = 0; nt < 8; nt++) {
                uint32_t p0 = hmax2z(hadd2u(accA[mt][nt][0], b1p[nt]));
                uint32_t p1 = hmax2z(hadd2u(accA[mt][nt][1], b1p[nt]));
                uint32_t by0 = ebm + (uint32_t)((nt ^ c0) * 16);
                *reinterpret_cast<uint32_t*>(smem + by0) = p0;
                *reinterpret_cast<uint32_t*>(smem + by0 + 4096) = p1;
            }
        }
    }
    #pragma unroll
    for (int a = 0; a < 4; a++)
        #pragma unroll
        for (int b = 0; b < 8; b++) {
            accA[a][b][0] = 0u; accA[a][b][1] = 0u;
            accB[a][b][0] = 0u; accB[a][b][1] = 0u;
        }

    __syncthreads();   // H1 visible

    // ---- layer 2 GEMM (K = 256): two 8-step f16 chains (accA, accB) ----
    gemm<16, 8, 512>(pb2, sb + OFF_H1, accA, accB, lane, breg);

    // ---- epilogue 2: v = hmax2(accA+accB+b2) in half2; dot w3 in f32 ----
    {
        uint32_t b2p[8];
        float2 w3f[8];
        #pragma unroll
        for (int nt = 0; nt < 8; nt++) {
            int idx = wn * 32 + nt * 4 + (lane & 3);
            b2p[nt] = smu[(OFF_B2 >> 2) + idx];
            w3f[nt] = __half22float2(u2h(smu[(OFF_W3 >> 2) + idx]));
        }
        float p[4][2];
        #pragma unroll
        for (int mt = 0; mt < 4; mt++) { p[mt][0] = 0.f; p[mt][1] = 0.f; }
        #pragma unroll
        for (int mt = 0; mt < 4; mt++)
            #pragma unroll
            for (int nt = 0; nt < 8; nt++)
                #pragma unroll
                for (int r2 = 0; r2 < 2; r2++) {
                    uint32_t s = hadd2u(accA[mt][nt][r2], accB[mt][nt][r2]);
                    uint32_t v = hmax2z(hadd2u(s, b2p[nt]));
                    float2 fv = __half22float2(u2h(v));
                    p[mt][r2] += fv.x * w3f[nt].x + fv.y * w3f[nt].y;
                }
        #pragma unroll
        for (int off = 1; off <= 2; off <<= 1)
            #pragma unroll
            for (int mt = 0; mt < 4; mt++) {
                p[mt][0] += __shfl_xor_sync(0xFFFFFFFFu, p[mt][0], off);
                p[mt][1] += __shfl_xor_sync(0xFFFFFFFFu, p[mt][1], off);
            }
        if ((lane & 3) == 0) {
            #pragma unroll
            for (int mt = 0; mt < 4; mt++)
                #pragma unroll
                for (int h = 0; h < 2; h++) {
                    int row = mt * 16 + (lane >> 2) + 8 * h;
                    smf[(OFF_PART >> 2) + row * 4 + wn] = p[mt][h];
                }
        }
    }
    __syncthreads();
    if (tid < BM) {
        const float* q = smf + (OFF_PART >> 2) + tid * 4;
        out[(size_t)(m0 + tid) * NEXP + c] = q[0] + q[1] + q[2] + q[3] + b3[c];
    }
}

extern "C" void kernel_launch(void* const* d_in, const int* in_sizes, int n_in,
                              void* d_out, int out_size)
{
    const float* st = (const float*)d_in[0];
    const float* W1 = (const float*)d_in[1];
    const float* b1 = (const float*)d_in[2];
    const float* W2 = (const float*)d_in[3];
    const float* b2 = (const float*)d_in[4];
    const float* W3 = (const float*)d_in[5];
    const float* b3 = (const float*)d_in[6];
    float* out = (float*)d_out;

    const int total = NEXP * 4 * 4 * 512 + NEXP * 4 * 16 * 512;  // 327680
    convw<<<(total + 255) / 256, 256>>>(W1, W2);

    cudaFuncSetAttribute(moe_disc_mma,
                         cudaFuncAttributeMaxDynamicSharedMemorySize, SMEM_BYTES);
    dim3 grid(65536 / BM, NEXP);
    moe_disc_mma<<<grid, NTHR, SMEM_BYTES>>>(st, b1, b2, W3, b3, out);
}